// round 6
// baseline (speedup 1.0000x reference)
#include <cuda_runtime.h>
#include <cuda_bf16.h>
#include <math.h>
#include <stdint.h>

#define T_TOKENS 4096
#define D_DIM    768
#define F_DIM    3072
#define E_EXP    8
#define EXP_CAP  4096
#define NSLOTS   (E_EXP * EXP_CAP)

// ------------------------------------------------------------------ scratch
__device__ int   g_fill[E_EXP];          // zeroed by memset each call
__device__ int   g_slot_token[NSLOTS];
__device__ float g_slot_w[NSLOTS];

__device__ __nv_bfloat16 g_ahi[(size_t)NSLOTS * D_DIM];
__device__ __nv_bfloat16 g_alo[(size_t)NSLOTS * D_DIM];
__device__ __nv_bfloat16 g_hhi[(size_t)NSLOTS * F_DIM];
__device__ __nv_bfloat16 g_hlo[(size_t)NSLOTS * F_DIM];
// transposed K-major weights: wfcT [E][F][D], wpjT [E][D][F]
__device__ __nv_bfloat16 g_wfchi[(size_t)E_EXP * F_DIM * D_DIM];
__device__ __nv_bfloat16 g_wfclo[(size_t)E_EXP * F_DIM * D_DIM];
__device__ __nv_bfloat16 g_wpjhi[(size_t)E_EXP * D_DIM * F_DIM];
__device__ __nv_bfloat16 g_wpjlo[(size_t)E_EXP * D_DIM * F_DIM];

// ------------------------------------------------------------------ helpers
__device__ __forceinline__ uint32_t smem_u32(const void* p) {
    uint32_t a;
    asm("{ .reg .u64 t; cvta.to.shared.u64 t, %1; cvt.u32.u64 %0, t; }" : "=r"(a) : "l"(p));
    return a;
}
__device__ __forceinline__ void cp16(uint32_t s, const void* g) {
    asm volatile("cp.async.cg.shared.global [%0], [%1], 16;" :: "r"(s), "l"(g));
}
#define CP_COMMIT() asm volatile("cp.async.commit_group;" ::: "memory")

__device__ __forceinline__ void ldsm4(uint32_t r[4], uint32_t addr) {
    asm volatile("ldmatrix.sync.aligned.m8n8.x4.shared.b16 {%0,%1,%2,%3}, [%4];"
                 : "=r"(r[0]), "=r"(r[1]), "=r"(r[2]), "=r"(r[3]) : "r"(addr));
}
__device__ __forceinline__ void mma16816(float c[4], const uint32_t a[4],
                                         uint32_t b0, uint32_t b1) {
    asm volatile("mma.sync.aligned.m16n8k16.row.col.f32.bf16.bf16.f32 "
                 "{%0,%1,%2,%3}, {%4,%5,%6,%7}, {%8,%9}, {%0,%1,%2,%3};"
                 : "+f"(c[0]), "+f"(c[1]), "+f"(c[2]), "+f"(c[3])
                 : "r"(a[0]), "r"(a[1]), "r"(a[2]), "r"(a[3]), "r"(b0), "r"(b1));
}

// ------------------------------------------------------------------ weight convert
__global__ void k_convw(const float* __restrict__ src, int K, int N, int which) {
    __shared__ float tile[32][33];
    __nv_bfloat16* dhi = which ? g_wpjhi : g_wfchi;
    __nv_bfloat16* dlo = which ? g_wpjlo : g_wfclo;
    int e = blockIdx.z;
    int n0 = blockIdx.x * 32, k0 = blockIdx.y * 32;
    const float* s = src + (size_t)e * K * N;
#pragma unroll
    for (int dy = 0; dy < 32; dy += 8)
        tile[threadIdx.y + dy][threadIdx.x] =
            s[(size_t)(k0 + threadIdx.y + dy) * N + n0 + threadIdx.x];
    __syncthreads();
    size_t db = (size_t)e * N * K;
#pragma unroll
    for (int dy = 0; dy < 32; dy += 8) {
        int n = n0 + threadIdx.y + dy, k = k0 + threadIdx.x;
        float v = tile[threadIdx.x][threadIdx.y + dy];
        __nv_bfloat16 h = __float2bfloat16(v);
        dhi[db + (size_t)n * K + k] = h;
        dlo[db + (size_t)n * K + k] = __float2bfloat16(v - __bfloat162float(h));
    }
}

// ------------------------------------------------------------------ fused router + slot fill + x split
__global__ void k_router(const float* __restrict__ x, const float* __restrict__ rw) {
    __shared__ float s_rw[E_EXP * D_DIM];
    for (int i = threadIdx.x; i < E_EXP * D_DIM; i += blockDim.x) s_rw[i] = rw[i];
    __syncthreads();
    int warp = threadIdx.x >> 5, lane = threadIdx.x & 31;
    int t = blockIdx.x * 8 + warp;
    if (t >= T_TOKENS) return;

    const float* xrow = x + (size_t)t * D_DIM;
    float xr[24];
#pragma unroll
    for (int i = 0; i < 24; i++) xr[i] = xrow[lane + 32 * i];

    float logit[E_EXP];
#pragma unroll
    for (int e = 0; e < E_EXP; e++) {
        float p = 0.f;
#pragma unroll
        for (int i = 0; i < 24; i++) p = fmaf(xr[i], s_rw[e * D_DIM + lane + 32 * i], p);
#pragma unroll
        for (int o = 16; o; o >>= 1) p += __shfl_xor_sync(0xffffffffu, p, o);
        logit[e] = p;
    }
    int slot0 = 0, slot1 = 0;
    if (lane == 0) {
        int e0 = 0; float v0 = logit[0];
#pragma unroll
        for (int e = 1; e < E_EXP; e++) if (logit[e] > v0) { v0 = logit[e]; e0 = e; }
        int e1 = 0; float v1 = -3.0e38f;
#pragma unroll
        for (int e = 0; e < E_EXP; e++) {
            if (e == e0) continue;
            if (logit[e] > v1) { v1 = logit[e]; e1 = e; }
        }
        float ex = expf(v1 - v0);
        float inv = 1.f / (1.f + ex);
        slot0 = e0 * EXP_CAP + atomicAdd(&g_fill[e0], 1);
        slot1 = e1 * EXP_CAP + atomicAdd(&g_fill[e1], 1);
        g_slot_token[slot0] = t;  g_slot_w[slot0] = inv;
        g_slot_token[slot1] = t;  g_slot_w[slot1] = ex * inv;
    }
    slot0 = __shfl_sync(0xffffffffu, slot0, 0);
    slot1 = __shfl_sync(0xffffffffu, slot1, 0);

#pragma unroll
    for (int i = 0; i < 24; i++) {
        float v = xr[i];
        __nv_bfloat16 h = __float2bfloat16(v);
        __nv_bfloat16 l = __float2bfloat16(v - __bfloat162float(h));
        int c = lane + 32 * i;
        g_ahi[(size_t)slot0 * D_DIM + c] = h;
        g_alo[(size_t)slot0 * D_DIM + c] = l;
        g_ahi[(size_t)slot1 * D_DIM + c] = h;
        g_alo[(size_t)slot1 * D_DIM + c] = l;
    }
}

// ------------------------------------------------------------------ mma.sync grouped GEMM
// CTA 128x128, 4 warps (warp tile 64x64), BK=32 with [hi 64B | lo 64B] packed rows.
// 3-stage cp.async pipe (32KB/stage, 96KB smem) -> 2 CTAs/SM.
// 3-pass bf16 split into fp32 accumulators. gemm2 uses split-K x2 (atomicAdd combine).
#define OFF_B 16384
#define STAGE_BYTES 32768
#define N_STAGES 3
#define GEMM_SMEM (N_STAGES * STAGE_BYTES + 1024)

__device__ __forceinline__ uint32_t sw_addr(uint32_t tbase, int row, int byte) {
    uint32_t b = (uint32_t)(row * 128 + byte);
    return tbase + (b ^ ((b >> 3) & 0x70));
}

template <bool IS_FC>
__global__ __launch_bounds__(128, 2)
void k_mma_gemm(const float* __restrict__ bias, float* __restrict__ out)
{
    constexpr int Kdim = IS_FC ? D_DIM : F_DIM;
    constexpr int Ndim = IS_FC ? F_DIM : D_DIM;
    constexpr int NC   = IS_FC ? (Kdim / 32) : (Kdim / 32 / 2);   // chunks this CTA

    const int zz     = blockIdx.z;
    const int e      = IS_FC ? zz : (zz >> 1);
    const int ksplit = IS_FC ? 0 : (zz & 1);
    const int kbase  = ksplit * NC;                               // chunk offset

    const int cnt = g_fill[e];
    const int off = e * EXP_CAP;
    const int m0  = blockIdx.x * 128;
    if (m0 >= cnt) return;
    const int n0 = blockIdx.y * 128;

    const __nv_bfloat16* Ahi = IS_FC ? g_ahi : g_hhi;
    const __nv_bfloat16* Alo = IS_FC ? g_alo : g_hlo;
    const __nv_bfloat16* Bhi = (IS_FC ? g_wfchi : g_wpjhi) + (size_t)e * Ndim * Kdim;
    const __nv_bfloat16* Blo = (IS_FC ? g_wfclo : g_wpjlo) + (size_t)e * Ndim * Kdim;

    extern __shared__ char smem_raw[];
    const uint32_t sbase = (smem_u32(smem_raw) + 1023) & ~1023u;

    const int tid = threadIdx.x;
    const int wid = tid >> 5, lid = tid & 31;
    const int wm = (wid >> 1) * 64;     // 2x2 warp grid
    const int wn = (wid & 1) * 64;

    // ---- global load mappings: per thread 8 A rows + 8 B rows, one 16B chunk each.
    // smem row = 128B = [hi 64B | lo 64B]; c16 0-3 pull from hi source, 4-7 from lo.
    const int c16 = tid & 7;
    const bool isLo = (c16 >= 4);
    const int kc = (c16 & 3) * 16;                 // byte offset within 64B k-slab
    const char* aSrc = (const char*)(isLo ? Alo : Ahi);
    const char* bSrc = (const char*)(isLo ? Blo : Bhi);

    size_t aOff[8], bOff[8];
    uint32_t sSw[8];
#pragma unroll
    for (int j = 0; j < 8; j++) {
        int row = (tid >> 3) + j * 16;             // 0..127
        int gr  = off + min(m0 + row, cnt - 1);
        aOff[j] = (size_t)gr * (Kdim * 2) + kc;
        bOff[j] = (size_t)(n0 + row) * (Kdim * 2) + kc;
        uint32_t b = (uint32_t)(row * 128 + c16 * 16);
        sSw[j] = b ^ ((b >> 3) & 0x70);
    }

    auto load_chunk = [&](int chunk, int st) {
        uint32_t sb = sbase + st * STAGE_BYTES;
        size_t ko = (size_t)(kbase + chunk) * 64;  // 32 cols * 2B per chunk
#pragma unroll
        for (int j = 0; j < 8; j++) cp16(sb + sSw[j], aSrc + aOff[j] + ko);
#pragma unroll
        for (int j = 0; j < 8; j++) cp16(sb + OFF_B + sSw[j], bSrc + bOff[j] + ko);
        CP_COMMIT();
    };

    float acc[4][8][4];
#pragma unroll
    for (int i = 0; i < 4; i++)
#pragma unroll
        for (int j = 0; j < 8; j++)
#pragma unroll
            for (int c = 0; c < 4; c++) acc[i][j][c] = 0.f;

    load_chunk(0, 0);
    if (NC > 1) load_chunk(1, 1);

    // ldmatrix lane addressing
    const int aRow = lid & 15;
    const int aHi16 = ((lid >> 4) & 1) * 16;
    const int bRowSel = ((lid >> 4) & 1) * 8 + (lid & 7);
    const int bHi16 = ((lid >> 3) & 1) * 16;

    for (int k = 0; k < NC; k++) {
        const int st = k % N_STAGES;
        if (k < NC - 1) asm volatile("cp.async.wait_group 1;" ::: "memory");
        else            asm volatile("cp.async.wait_group 0;" ::: "memory");
        __syncthreads();
        if (k + 2 < NC) load_chunk(k + 2, (k + 2) % N_STAGES);

        const uint32_t tA = sbase + st * STAGE_BYTES;
        const uint32_t tB = tA + OFF_B;

#pragma unroll
        for (int q = 0; q < 2; q++) {              // 2 k16 steps per 32-chunk
            uint32_t ah[4][4], al[4][4], bh[4][4], bl[4][4];
#pragma unroll
            for (int mi = 0; mi < 4; mi++) {
                uint32_t adr = sw_addr(tA, wm + mi * 16 + aRow, q * 32 + aHi16);
                ldsm4(ah[mi], adr);
            }
#pragma unroll
            for (int nj2 = 0; nj2 < 4; nj2++) {
                uint32_t adr = sw_addr(tB, wn + nj2 * 16 + bRowSel, q * 32 + bHi16);
                ldsm4(bh[nj2], adr);
            }
#pragma unroll
            for (int mi = 0; mi < 4; mi++) {
                uint32_t adr = sw_addr(tA, wm + mi * 16 + aRow, 64 + q * 32 + aHi16);
                ldsm4(al[mi], adr);
            }
#pragma unroll
            for (int nj2 = 0; nj2 < 4; nj2++) {
                uint32_t adr = sw_addr(tB, wn + nj2 * 16 + bRowSel, 64 + q * 32 + bHi16);
                ldsm4(bl[nj2], adr);
            }
#pragma unroll
            for (int mi = 0; mi < 4; mi++)
#pragma unroll
                for (int nj = 0; nj < 8; nj++) {
                    uint32_t b0 = bh[nj >> 1][(nj & 1) * 2];
                    uint32_t b1 = bh[nj >> 1][(nj & 1) * 2 + 1];
                    uint32_t l0 = bl[nj >> 1][(nj & 1) * 2];
                    uint32_t l1 = bl[nj >> 1][(nj & 1) * 2 + 1];
                    mma16816(acc[mi][nj], ah[mi], b0, b1);
                    mma16816(acc[mi][nj], ah[mi], l0, l1);
                    mma16816(acc[mi][nj], al[mi], b0, b1);
                }
        }
    }

    // ---- epilogue ----
    const float* bp = bias + (size_t)e * Ndim + n0;
    const bool addb = IS_FC || (ksplit == 0);
    const int rbase = wm + (lid >> 2);
    const int cquad = (lid & 3) * 2;

#pragma unroll
    for (int mi = 0; mi < 4; mi++) {
#pragma unroll
        for (int half = 0; half < 2; half++) {
            const int row = rbase + mi * 16 + half * 8;
            const int m = m0 + row;
            if (m >= cnt) continue;
            const int slot = off + m;
            int tok = 0; float wgt = 0.f;
            if (!IS_FC) { tok = g_slot_token[slot]; wgt = g_slot_w[slot]; }
#pragma unroll
            for (int nj = 0; nj < 8; nj++) {
                const int col = wn + nj * 8 + cquad;
                float b0 = addb ? bp[col] : 0.f;
                float b1 = addb ? bp[col + 1] : 0.f;
                float v0 = acc[mi][nj][half * 2 + 0] + b0;
                float v1 = acc[mi][nj][half * 2 + 1] + b1;
                if (IS_FC) {
                    float g0 = 0.5f * v0 * (1.f + erff(v0 * 0.70710678118654752f));
                    float g1 = 0.5f * v1 * (1.f + erff(v1 * 0.70710678118654752f));
                    __nv_bfloat16 h0 = __float2bfloat16(g0);
                    __nv_bfloat16 h1 = __float2bfloat16(g1);
                    __nv_bfloat16 q0 = __float2bfloat16(g0 - __bfloat162float(h0));
                    __nv_bfloat16 q1 = __float2bfloat16(g1 - __bfloat162float(h1));
                    size_t idx = (size_t)slot * Ndim + n0 + col;
                    *(uint32_t*)(g_hhi + idx) =
                        (uint32_t)__bfloat16_as_ushort(h0) |
                        ((uint32_t)__bfloat16_as_ushort(h1) << 16);
                    *(uint32_t*)(g_hlo + idx) =
                        (uint32_t)__bfloat16_as_ushort(q0) |
                        ((uint32_t)__bfloat16_as_ushort(q1) << 16);
                } else {
                    float* op = out + (size_t)tok * D_DIM + n0 + col;
                    atomicAdd(op + 0, v0 * wgt);
                    atomicAdd(op + 1, v1 * wgt);
                }
            }
        }
    }
}

// ------------------------------------------------------------------ launch
extern "C" void kernel_launch(void* const* d_in, const int* in_sizes, int n_in,
                              void* d_out, int out_size)
{
    const float* x      = (const float*)d_in[0];
    const float* rw     = (const float*)d_in[1];
    const float* w_fc   = (const float*)d_in[2];
    const float* b_fc   = (const float*)d_in[3];
    const float* w_proj = (const float*)d_in[4];
    const float* b_proj = (const float*)d_in[5];
    float* out = (float*)d_out;

    cudaFuncSetAttribute(k_mma_gemm<true>,  cudaFuncAttributeMaxDynamicSharedMemorySize, GEMM_SMEM);
    cudaFuncSetAttribute(k_mma_gemm<false>, cudaFuncAttributeMaxDynamicSharedMemorySize, GEMM_SMEM);

    cudaMemsetAsync(out, 0, (size_t)out_size * sizeof(float));
    void* pfill = nullptr;
    cudaGetSymbolAddress(&pfill, g_fill);
    cudaMemsetAsync(pfill, 0, E_EXP * sizeof(int));

    dim3 bw(32, 8);
    k_convw<<<dim3(F_DIM / 32, D_DIM / 32, E_EXP), bw>>>(w_fc,   D_DIM, F_DIM, 0);  // #1
    k_convw<<<dim3(D_DIM / 32, F_DIM / 32, E_EXP), bw>>>(w_proj, F_DIM, D_DIM, 1);  // #2

    k_router<<<T_TOKENS / 8, 256>>>(x, rw);                                          // #3

    // gemm1: CTA tile 128x128, grid (M blocks, N blocks, experts)          #4 (profiled)
    k_mma_gemm<true ><<<dim3(EXP_CAP / 128, F_DIM / 128, E_EXP), 128, GEMM_SMEM>>>(b_fc, nullptr);
    // gemm2: split-K x2 -> grid.z = 2*experts                              #5
    k_mma_gemm<false><<<dim3(EXP_CAP / 128, D_DIM / 128, E_EXP * 2), 128, GEMM_SMEM>>>(b_proj, out);
}

// round 7
// speedup vs baseline: 1.0764x; 1.0764x over previous
#include <cuda_runtime.h>
#include <cuda_bf16.h>
#include <math.h>
#include <stdint.h>

#define T_TOKENS 4096
#define D_DIM    768
#define F_DIM    3072
#define E_EXP    8
#define EXP_CAP  4096
#define NSLOTS   (E_EXP * EXP_CAP)

// ------------------------------------------------------------------ scratch
__device__ int   g_fill[E_EXP];          // zeroed by memset each call
__device__ int   g_slot_token[NSLOTS];
__device__ float g_slot_w[NSLOTS];

__device__ __nv_bfloat16 g_ahi[(size_t)NSLOTS * D_DIM];
__device__ __nv_bfloat16 g_alo[(size_t)NSLOTS * D_DIM];
__device__ __nv_bfloat16 g_hhi[(size_t)NSLOTS * F_DIM];
__device__ __nv_bfloat16 g_hlo[(size_t)NSLOTS * F_DIM];
// transposed K-major weights: wfcT [E][F][D], wpjT [E][D][F]
__device__ __nv_bfloat16 g_wfchi[(size_t)E_EXP * F_DIM * D_DIM];
__device__ __nv_bfloat16 g_wfclo[(size_t)E_EXP * F_DIM * D_DIM];
__device__ __nv_bfloat16 g_wpjhi[(size_t)E_EXP * D_DIM * F_DIM];
__device__ __nv_bfloat16 g_wpjlo[(size_t)E_EXP * D_DIM * F_DIM];

// ------------------------------------------------------------------ helpers
__device__ __forceinline__ uint32_t smem_u32(const void* p) {
    uint32_t a;
    asm("{ .reg .u64 t; cvta.to.shared.u64 t, %1; cvt.u32.u64 %0, t; }" : "=r"(a) : "l"(p));
    return a;
}
__device__ __forceinline__ void cp16(uint32_t s, const void* g) {
    asm volatile("cp.async.cg.shared.global [%0], [%1], 16;" :: "r"(s), "l"(g));
}
#define CP_COMMIT() asm volatile("cp.async.commit_group;" ::: "memory")

__device__ __forceinline__ void ldsm4(uint32_t r[4], uint32_t addr) {
    asm volatile("ldmatrix.sync.aligned.m8n8.x4.shared.b16 {%0,%1,%2,%3}, [%4];"
                 : "=r"(r[0]), "=r"(r[1]), "=r"(r[2]), "=r"(r[3]) : "r"(addr));
}
__device__ __forceinline__ void mma16816(float c[4], const uint32_t a[4],
                                         uint32_t b0, uint32_t b1) {
    asm volatile("mma.sync.aligned.m16n8k16.row.col.f32.bf16.bf16.f32 "
                 "{%0,%1,%2,%3}, {%4,%5,%6,%7}, {%8,%9}, {%0,%1,%2,%3};"
                 : "+f"(c[0]), "+f"(c[1]), "+f"(c[2]), "+f"(c[3])
                 : "r"(a[0]), "r"(a[1]), "r"(a[2]), "r"(a[3]), "r"(b0), "r"(b1));
}

// ------------------------------------------------------------------ weight convert
__global__ void k_convw(const float* __restrict__ src, int K, int N, int which) {
    __shared__ float tile[32][33];
    __nv_bfloat16* dhi = which ? g_wpjhi : g_wfchi;
    __nv_bfloat16* dlo = which ? g_wpjlo : g_wfclo;
    int e = blockIdx.z;
    int n0 = blockIdx.x * 32, k0 = blockIdx.y * 32;
    const float* s = src + (size_t)e * K * N;
#pragma unroll
    for (int dy = 0; dy < 32; dy += 8)
        tile[threadIdx.y + dy][threadIdx.x] =
            s[(size_t)(k0 + threadIdx.y + dy) * N + n0 + threadIdx.x];
    __syncthreads();
    size_t db = (size_t)e * N * K;
#pragma unroll
    for (int dy = 0; dy < 32; dy += 8) {
        int n = n0 + threadIdx.y + dy, k = k0 + threadIdx.x;
        float v = tile[threadIdx.x][threadIdx.y + dy];
        __nv_bfloat16 h = __float2bfloat16(v);
        dhi[db + (size_t)n * K + k] = h;
        dlo[db + (size_t)n * K + k] = __float2bfloat16(v - __bfloat162float(h));
    }
}

// ------------------------------------------------------------------ fused router + slot fill + x split
__global__ void k_router(const float* __restrict__ x, const float* __restrict__ rw) {
    __shared__ float s_rw[E_EXP * D_DIM];
    for (int i = threadIdx.x; i < E_EXP * D_DIM; i += blockDim.x) s_rw[i] = rw[i];
    __syncthreads();
    int warp = threadIdx.x >> 5, lane = threadIdx.x & 31;
    int t = blockIdx.x * 8 + warp;
    if (t >= T_TOKENS) return;

    const float* xrow = x + (size_t)t * D_DIM;
    float xr[24];
#pragma unroll
    for (int i = 0; i < 24; i++) xr[i] = xrow[lane + 32 * i];

    float logit[E_EXP];
#pragma unroll
    for (int e = 0; e < E_EXP; e++) {
        float p = 0.f;
#pragma unroll
        for (int i = 0; i < 24; i++) p = fmaf(xr[i], s_rw[e * D_DIM + lane + 32 * i], p);
#pragma unroll
        for (int o = 16; o; o >>= 1) p += __shfl_xor_sync(0xffffffffu, p, o);
        logit[e] = p;
    }
    int slot0 = 0, slot1 = 0;
    if (lane == 0) {
        int e0 = 0; float v0 = logit[0];
#pragma unroll
        for (int e = 1; e < E_EXP; e++) if (logit[e] > v0) { v0 = logit[e]; e0 = e; }
        int e1 = 0; float v1 = -3.0e38f;
#pragma unroll
        for (int e = 0; e < E_EXP; e++) {
            if (e == e0) continue;
            if (logit[e] > v1) { v1 = logit[e]; e1 = e; }
        }
        float ex = expf(v1 - v0);
        float inv = 1.f / (1.f + ex);
        slot0 = e0 * EXP_CAP + atomicAdd(&g_fill[e0], 1);
        slot1 = e1 * EXP_CAP + atomicAdd(&g_fill[e1], 1);
        g_slot_token[slot0] = t;  g_slot_w[slot0] = inv;
        g_slot_token[slot1] = t;  g_slot_w[slot1] = ex * inv;
    }
    slot0 = __shfl_sync(0xffffffffu, slot0, 0);
    slot1 = __shfl_sync(0xffffffffu, slot1, 0);

#pragma unroll
    for (int i = 0; i < 24; i++) {
        float v = xr[i];
        __nv_bfloat16 h = __float2bfloat16(v);
        __nv_bfloat16 l = __float2bfloat16(v - __bfloat162float(h));
        int c = lane + 32 * i;
        g_ahi[(size_t)slot0 * D_DIM + c] = h;
        g_alo[(size_t)slot0 * D_DIM + c] = l;
        g_ahi[(size_t)slot1 * D_DIM + c] = h;
        g_alo[(size_t)slot1 * D_DIM + c] = l;
    }
}

// ------------------------------------------------------------------ mma.sync grouped GEMM
// CTA 128x64, 4 warps (warp tile 64x32), BK=32 with [hi 64B | lo 64B] packed rows.
// 3-stage cp.async pipe (24KB/stage, 72KB smem) -> 3 CTAs/SM (12 warps) for
// cross-CTA latency hiding; fragments single-buffered to fit 170 regs.
// 3-pass bf16 split into fp32 accumulators. gemm2 uses split-K x2 (atomicAdd combine).
#define OFF_B 16384
#define STAGE_BYTES 24576
#define N_STAGES 3
#define GEMM_SMEM (N_STAGES * STAGE_BYTES + 1024)

__device__ __forceinline__ uint32_t sw_addr(uint32_t tbase, int row, int byte) {
    uint32_t b = (uint32_t)(row * 128 + byte);
    return tbase + (b ^ ((b >> 3) & 0x70));
}

template <bool IS_FC>
__global__ __launch_bounds__(128, 3)
void k_mma_gemm(const float* __restrict__ bias, float* __restrict__ out)
{
    constexpr int Kdim = IS_FC ? D_DIM : F_DIM;
    constexpr int Ndim = IS_FC ? F_DIM : D_DIM;
    constexpr int NC   = IS_FC ? (Kdim / 32) : (Kdim / 32 / 2);   // chunks this CTA

    const int zz     = blockIdx.z;
    const int e      = IS_FC ? zz : (zz >> 1);
    const int ksplit = IS_FC ? 0 : (zz & 1);
    const int kbase  = ksplit * NC;

    const int cnt = g_fill[e];
    const int off = e * EXP_CAP;
    const int m0  = blockIdx.x * 128;
    if (m0 >= cnt) return;
    const int n0 = blockIdx.y * 64;

    const __nv_bfloat16* Ahi = IS_FC ? g_ahi : g_hhi;
    const __nv_bfloat16* Alo = IS_FC ? g_alo : g_hlo;
    const __nv_bfloat16* Bhi = (IS_FC ? g_wfchi : g_wpjhi) + (size_t)e * Ndim * Kdim;
    const __nv_bfloat16* Blo = (IS_FC ? g_wfclo : g_wpjlo) + (size_t)e * Ndim * Kdim;

    extern __shared__ char smem_raw[];
    const uint32_t sbase = (smem_u32(smem_raw) + 1023) & ~1023u;

    const int tid = threadIdx.x;
    const int wid = tid >> 5, lid = tid & 31;
    const int wm = (wid >> 1) * 64;     // 2x2 warp grid over 128x64
    const int wn = (wid & 1) * 32;

    // ---- global load mappings: smem row = 128B = [hi 64B | lo 64B].
    // c16 0-3 pull 16B chunks from the hi source, 4-7 from the lo source.
    const int c16 = tid & 7;
    const bool isLo = (c16 >= 4);
    const int kc = (c16 & 3) * 16;                 // byte offset within 64B k-slab
    const char* aSrc = (const char*)(isLo ? Alo : Ahi);
    const char* bSrc = (const char*)(isLo ? Blo : Bhi);

    // 32-bit byte offsets (all arrays < 256 MB)
    uint32_t aOff[8], bOff[4], aSw[8], bSw[4];
#pragma unroll
    for (int j = 0; j < 8; j++) {
        int row = (tid >> 3) + j * 16;             // 0..127
        int gr  = off + min(m0 + row, cnt - 1);
        aOff[j] = (uint32_t)gr * (uint32_t)(Kdim * 2) + (uint32_t)kc;
        uint32_t b = (uint32_t)(row * 128 + c16 * 16);
        aSw[j] = b ^ ((b >> 3) & 0x70);
    }
#pragma unroll
    for (int j = 0; j < 4; j++) {
        int row = (tid >> 3) + j * 16;             // 0..63
        bOff[j] = (uint32_t)(n0 + row) * (uint32_t)(Kdim * 2) + (uint32_t)kc;
        uint32_t b = (uint32_t)(row * 128 + c16 * 16);
        bSw[j] = b ^ ((b >> 3) & 0x70);
    }

    auto load_chunk = [&](int chunk, int st) {
        uint32_t sb = sbase + st * STAGE_BYTES;
        uint32_t ko = (uint32_t)(kbase + chunk) * 64u;   // 32 cols * 2B
#pragma unroll
        for (int j = 0; j < 8; j++) cp16(sb + aSw[j], aSrc + aOff[j] + ko);
#pragma unroll
        for (int j = 0; j < 4; j++) cp16(sb + OFF_B + bSw[j], bSrc + bOff[j] + ko);
        CP_COMMIT();
    };

    float acc[4][4][4];
#pragma unroll
    for (int i = 0; i < 4; i++)
#pragma unroll
        for (int j = 0; j < 4; j++)
#pragma unroll
            for (int c = 0; c < 4; c++) acc[i][j][c] = 0.f;

    load_chunk(0, 0);
    load_chunk(1, 1);

    // ldmatrix lane addressing
    const int aRow = lid & 15;
    const int aHi16 = ((lid >> 4) & 1) * 16;
    const int bRowSel = ((lid >> 4) & 1) * 8 + (lid & 7);
    const int bHi16 = ((lid >> 3) & 1) * 16;

    for (int k = 0; k < NC; k++) {
        const int st = k % N_STAGES;
        if (k < NC - 1) asm volatile("cp.async.wait_group 1;" ::: "memory");
        else            asm volatile("cp.async.wait_group 0;" ::: "memory");
        __syncthreads();
        if (k + 2 < NC) load_chunk(k + 2, (k + 2) % N_STAGES);

        const uint32_t tA = sbase + st * STAGE_BYTES;
        const uint32_t tB = tA + OFF_B;

#pragma unroll
        for (int q = 0; q < 2; q++) {              // 2 k16 steps per 32-chunk
            uint32_t ah[4][4], al[4][4], bh[2][4], bl[2][4];
#pragma unroll
            for (int mi = 0; mi < 4; mi++) {
                uint32_t adr = sw_addr(tA, wm + mi * 16 + aRow, q * 32 + aHi16);
                ldsm4(ah[mi], adr);
            }
#pragma unroll
            for (int nj2 = 0; nj2 < 2; nj2++) {
                uint32_t adr = sw_addr(tB, wn + nj2 * 16 + bRowSel, q * 32 + bHi16);
                ldsm4(bh[nj2], adr);
            }
#pragma unroll
            for (int mi = 0; mi < 4; mi++) {
                uint32_t adr = sw_addr(tA, wm + mi * 16 + aRow, 64 + q * 32 + aHi16);
                ldsm4(al[mi], adr);
            }
#pragma unroll
            for (int nj2 = 0; nj2 < 2; nj2++) {
                uint32_t adr = sw_addr(tB, wn + nj2 * 16 + bRowSel, 64 + q * 32 + bHi16);
                ldsm4(bl[nj2], adr);
            }
#pragma unroll
            for (int mi = 0; mi < 4; mi++)
#pragma unroll
                for (int nj = 0; nj < 4; nj++) {
                    uint32_t b0 = bh[nj >> 1][(nj & 1) * 2];
                    uint32_t b1 = bh[nj >> 1][(nj & 1) * 2 + 1];
                    uint32_t l0 = bl[nj >> 1][(nj & 1) * 2];
                    uint32_t l1 = bl[nj >> 1][(nj & 1) * 2 + 1];
                    mma16816(acc[mi][nj], ah[mi], b0, b1);
                    mma16816(acc[mi][nj], ah[mi], l0, l1);
                    mma16816(acc[mi][nj], al[mi], b0, b1);
                }
        }
    }

    // ---- epilogue ----
    const float* bp = bias + (size_t)e * Ndim + n0;
    const bool addb = IS_FC || (ksplit == 0);
    const int rbase = wm + (lid >> 2);
    const int cquad = (lid & 3) * 2;

#pragma unroll
    for (int mi = 0; mi < 4; mi++) {
#pragma unroll
        for (int half = 0; half < 2; half++) {
            const int row = rbase + mi * 16 + half * 8;
            const int m = m0 + row;
            if (m >= cnt) continue;
            const int slot = off + m;
            int tok = 0; float wgt = 0.f;
            if (!IS_FC) { tok = g_slot_token[slot]; wgt = g_slot_w[slot]; }
#pragma unroll
            for (int nj = 0; nj < 4; nj++) {
                const int col = wn + nj * 8 + cquad;
                float b0 = addb ? bp[col] : 0.f;
                float b1 = addb ? bp[col + 1] : 0.f;
                float v0 = acc[mi][nj][half * 2 + 0] + b0;
                float v1 = acc[mi][nj][half * 2 + 1] + b1;
                if (IS_FC) {
                    float g0 = 0.5f * v0 * (1.f + erff(v0 * 0.70710678118654752f));
                    float g1 = 0.5f * v1 * (1.f + erff(v1 * 0.70710678118654752f));
                    __nv_bfloat16 h0 = __float2bfloat16(g0);
                    __nv_bfloat16 h1 = __float2bfloat16(g1);
                    __nv_bfloat16 q0 = __float2bfloat16(g0 - __bfloat162float(h0));
                    __nv_bfloat16 q1 = __float2bfloat16(g1 - __bfloat162float(h1));
                    size_t idx = (size_t)slot * Ndim + n0 + col;
                    *(uint32_t*)(g_hhi + idx) =
                        (uint32_t)__bfloat16_as_ushort(h0) |
                        ((uint32_t)__bfloat16_as_ushort(h1) << 16);
                    *(uint32_t*)(g_hlo + idx) =
                        (uint32_t)__bfloat16_as_ushort(q0) |
                        ((uint32_t)__bfloat16_as_ushort(q1) << 16);
                } else {
                    float* op = out + (size_t)tok * D_DIM + n0 + col;
                    atomicAdd(op + 0, v0 * wgt);
                    atomicAdd(op + 1, v1 * wgt);
                }
            }
        }
    }
}

// ------------------------------------------------------------------ launch
extern "C" void kernel_launch(void* const* d_in, const int* in_sizes, int n_in,
                              void* d_out, int out_size)
{
    const float* x      = (const float*)d_in[0];
    const float* rw     = (const float*)d_in[1];
    const float* w_fc   = (const float*)d_in[2];
    const float* b_fc   = (const float*)d_in[3];
    const float* w_proj = (const float*)d_in[4];
    const float* b_proj = (const float*)d_in[5];
    float* out = (float*)d_out;

    cudaFuncSetAttribute(k_mma_gemm<true>,  cudaFuncAttributeMaxDynamicSharedMemorySize, GEMM_SMEM);
    cudaFuncSetAttribute(k_mma_gemm<false>, cudaFuncAttributeMaxDynamicSharedMemorySize, GEMM_SMEM);

    cudaMemsetAsync(out, 0, (size_t)out_size * sizeof(float));
    void* pfill = nullptr;
    cudaGetSymbolAddress(&pfill, g_fill);
    cudaMemsetAsync(pfill, 0, E_EXP * sizeof(int));

    dim3 bw(32, 8);
    k_convw<<<dim3(F_DIM / 32, D_DIM / 32, E_EXP), bw>>>(w_fc,   D_DIM, F_DIM, 0);  // #1
    k_convw<<<dim3(D_DIM / 32, F_DIM / 32, E_EXP), bw>>>(w_proj, F_DIM, D_DIM, 1);  // #2

    k_router<<<T_TOKENS / 8, 256>>>(x, rw);                                          // #3

    // gemm1: CTA tile 128x64                                               #4 (profiled)
    k_mma_gemm<true ><<<dim3(EXP_CAP / 128, F_DIM / 64, E_EXP), 128, GEMM_SMEM>>>(b_fc, nullptr);
    // gemm2: split-K x2 -> grid.z = 2*experts                              #5
    k_mma_gemm<false><<<dim3(EXP_CAP / 128, D_DIM / 64, E_EXP * 2), 128, GEMM_SMEM>>>(b_proj, out);
}

// round 8
// speedup vs baseline: 1.3554x; 1.2592x over previous
#include <cuda_runtime.h>
#include <cuda_fp16.h>
#include <math.h>
#include <stdint.h>

#define T_TOKENS 4096
#define D_DIM    768
#define F_DIM    3072
#define E_EXP    8
#define EXP_CAP  4096
#define NSLOTS   (E_EXP * EXP_CAP)

// ------------------------------------------------------------------ scratch
__device__ int   g_fill[E_EXP];          // zeroed by memset each call
__device__ int   g_slot_token[NSLOTS];
__device__ float g_slot_w[NSLOTS];

__device__ __half g_a[(size_t)NSLOTS * D_DIM];   // x gathered, fp16 (single)
__device__ __half g_h[(size_t)NSLOTS * F_DIM];   // gelu(fc), fp16 (single)
// transposed K-major weights, exact 2-term fp16 split: wfcT [E][F][D], wpjT [E][D][F]
__device__ __half g_wfchi[(size_t)E_EXP * F_DIM * D_DIM];
__device__ __half g_wfclo[(size_t)E_EXP * F_DIM * D_DIM];
__device__ __half g_wpjhi[(size_t)E_EXP * D_DIM * F_DIM];
__device__ __half g_wpjlo[(size_t)E_EXP * D_DIM * F_DIM];

// ------------------------------------------------------------------ helpers
__device__ __forceinline__ uint32_t smem_u32(const void* p) {
    uint32_t a;
    asm("{ .reg .u64 t; cvta.to.shared.u64 t, %1; cvt.u32.u64 %0, t; }" : "=r"(a) : "l"(p));
    return a;
}
__device__ __forceinline__ void cp16(uint32_t s, const void* g) {
    asm volatile("cp.async.cg.shared.global [%0], [%1], 16;" :: "r"(s), "l"(g));
}
#define CP_COMMIT() asm volatile("cp.async.commit_group;" ::: "memory")

__device__ __forceinline__ void ldsm4(uint32_t r[4], uint32_t addr) {
    asm volatile("ldmatrix.sync.aligned.m8n8.x4.shared.b16 {%0,%1,%2,%3}, [%4];"
                 : "=r"(r[0]), "=r"(r[1]), "=r"(r[2]), "=r"(r[3]) : "r"(addr));
}
__device__ __forceinline__ void mma16816(float c[4], const uint32_t a[4],
                                         uint32_t b0, uint32_t b1) {
    asm volatile("mma.sync.aligned.m16n8k16.row.col.f32.f16.f16.f32 "
                 "{%0,%1,%2,%3}, {%4,%5,%6,%7}, {%8,%9}, {%0,%1,%2,%3};"
                 : "+f"(c[0]), "+f"(c[1]), "+f"(c[2]), "+f"(c[3])
                 : "r"(a[0]), "r"(a[1]), "r"(a[2]), "r"(a[3]), "r"(b0), "r"(b1));
}

// ------------------------------------------------------------------ weight convert
// transpose + exact fp16 split: src [E][K][N] fp32 -> dst [E][N][K] fp16 hi/lo
__global__ void k_convw(const float* __restrict__ src, int K, int N, int which) {
    __shared__ float tile[32][33];
    __half* dhi = which ? g_wpjhi : g_wfchi;
    __half* dlo = which ? g_wpjlo : g_wfclo;
    int e = blockIdx.z;
    int n0 = blockIdx.x * 32, k0 = blockIdx.y * 32;
    const float* s = src + (size_t)e * K * N;
#pragma unroll
    for (int dy = 0; dy < 32; dy += 8)
        tile[threadIdx.y + dy][threadIdx.x] =
            s[(size_t)(k0 + threadIdx.y + dy) * N + n0 + threadIdx.x];
    __syncthreads();
    size_t db = (size_t)e * N * K;
#pragma unroll
    for (int dy = 0; dy < 32; dy += 8) {
        int n = n0 + threadIdx.y + dy, k = k0 + threadIdx.x;
        float v = tile[threadIdx.x][threadIdx.y + dy];
        __half h = __float2half(v);
        dhi[db + (size_t)n * K + k] = h;
        dlo[db + (size_t)n * K + k] = __float2half(v - __half2float(h));
    }
}

// ------------------------------------------------------------------ fused router + slot fill + x->fp16
__global__ void k_router(const float* __restrict__ x, const float* __restrict__ rw) {
    __shared__ float s_rw[E_EXP * D_DIM];
    for (int i = threadIdx.x; i < E_EXP * D_DIM; i += blockDim.x) s_rw[i] = rw[i];
    __syncthreads();
    int warp = threadIdx.x >> 5, lane = threadIdx.x & 31;
    int t = blockIdx.x * 8 + warp;
    if (t >= T_TOKENS) return;

    const float* xrow = x + (size_t)t * D_DIM;
    float xr[24];
#pragma unroll
    for (int i = 0; i < 24; i++) xr[i] = xrow[lane + 32 * i];

    float logit[E_EXP];
#pragma unroll
    for (int e = 0; e < E_EXP; e++) {
        float p = 0.f;
#pragma unroll
        for (int i = 0; i < 24; i++) p = fmaf(xr[i], s_rw[e * D_DIM + lane + 32 * i], p);
#pragma unroll
        for (int o = 16; o; o >>= 1) p += __shfl_xor_sync(0xffffffffu, p, o);
        logit[e] = p;
    }
    int slot0 = 0, slot1 = 0;
    if (lane == 0) {
        int e0 = 0; float v0 = logit[0];
#pragma unroll
        for (int e = 1; e < E_EXP; e++) if (logit[e] > v0) { v0 = logit[e]; e0 = e; }
        int e1 = 0; float v1 = -3.0e38f;
#pragma unroll
        for (int e = 0; e < E_EXP; e++) {
            if (e == e0) continue;
            if (logit[e] > v1) { v1 = logit[e]; e1 = e; }
        }
        float ex = expf(v1 - v0);
        float inv = 1.f / (1.f + ex);
        slot0 = e0 * EXP_CAP + atomicAdd(&g_fill[e0], 1);
        slot1 = e1 * EXP_CAP + atomicAdd(&g_fill[e1], 1);
        g_slot_token[slot0] = t;  g_slot_w[slot0] = inv;
        g_slot_token[slot1] = t;  g_slot_w[slot1] = ex * inv;
    }
    slot0 = __shfl_sync(0xffffffffu, slot0, 0);
    slot1 = __shfl_sync(0xffffffffu, slot1, 0);

#pragma unroll
    for (int i = 0; i < 24; i++) {
        __half h = __float2half(xr[i]);
        int c = lane + 32 * i;
        g_a[(size_t)slot0 * D_DIM + c] = h;
        g_a[(size_t)slot1 * D_DIM + c] = h;
    }
}

// ------------------------------------------------------------------ mma.sync grouped GEMM
// CTA 128x64, 4 warps (warp tile 64x32), fp16 2-pass split: A*Bhi + A*Blo.
// Chunk = K64. Stage 32KB: A 128x128B (SW128) + B two half-chunks 64x[hi64|lo64].
// 3 stages (96KB) -> 2 CTAs/SM. gemm2 uses split-K x2 (atomicAdd combine).
#define OFF_B 16384
#define STAGE_BYTES 32768
#define N_STAGES 3
#define GEMM_SMEM (N_STAGES * STAGE_BYTES + 1024)

__device__ __forceinline__ uint32_t sw_addr(uint32_t tbase, int row, int byte) {
    uint32_t b = (uint32_t)(row * 128 + byte);
    return tbase + (b ^ ((b >> 3) & 0x70));
}

template <bool IS_FC>
__global__ __launch_bounds__(128, 2)
void k_mma_gemm(const float* __restrict__ bias, float* __restrict__ out)
{
    constexpr int Kdim = IS_FC ? D_DIM : F_DIM;
    constexpr int Ndim = IS_FC ? F_DIM : D_DIM;
    constexpr int NC   = IS_FC ? (Kdim / 64) : (Kdim / 64 / 2);   // K64 chunks this CTA

    const int zz     = blockIdx.z;
    const int e      = IS_FC ? zz : (zz >> 1);
    const int ksplit = IS_FC ? 0 : (zz & 1);
    const int kbase  = ksplit * NC;

    const int cnt = g_fill[e];
    const int off = e * EXP_CAP;
    const int m0  = blockIdx.x * 128;
    if (m0 >= cnt) return;
    const int n0 = blockIdx.y * 64;

    const __half* Asrc = IS_FC ? g_a : g_h;
    const __half* Bhi  = (IS_FC ? g_wfchi : g_wpjhi) + (size_t)e * Ndim * Kdim;
    const __half* Blo  = (IS_FC ? g_wfclo : g_wpjlo) + (size_t)e * Ndim * Kdim;

    extern __shared__ char smem_raw[];
    const uint32_t sbase = (smem_u32(smem_raw) + 1023) & ~1023u;

    const int tid = threadIdx.x;
    const int wid = tid >> 5, lid = tid & 31;
    const int wm = (wid >> 1) * 64;     // 2x2 warp grid over 128x64
    const int wn = (wid & 1) * 32;

    // ---- A loads: 128 rows x 128B (64 fp16), c16 = tid&7 covers full row ----
    const int c16 = tid & 7;
    uint32_t aOff[8], aSw[8];
#pragma unroll
    for (int j = 0; j < 8; j++) {
        int row = (tid >> 3) + j * 16;             // 0..127
        int gr  = off + min(m0 + row, cnt - 1);
        aOff[j] = (uint32_t)gr * (uint32_t)(Kdim * 2) + (uint32_t)(c16 * 16);
        uint32_t b = (uint32_t)(row * 128 + c16 * 16);
        aSw[j] = b ^ ((b >> 3) & 0x70);
    }
    // ---- B loads: per half-chunk 64 rows x [hi 64B | lo 64B]; c16 0-3 hi, 4-7 lo ----
    const bool isLo = (c16 >= 4);
    const int kc = (c16 & 3) * 16;                 // byte offset within 64B k-slab
    const char* bSrc = (const char*)(isLo ? Blo : Bhi);
    uint32_t bOff[4], bSw[4];
#pragma unroll
    for (int j = 0; j < 4; j++) {
        int row = (tid >> 3) + j * 16;             // 0..63
        bOff[j] = (uint32_t)(n0 + row) * (uint32_t)(Kdim * 2) + (uint32_t)kc;
        uint32_t b = (uint32_t)(row * 128 + c16 * 16);
        bSw[j] = b ^ ((b >> 3) & 0x70);
    }
    const char* aSrcC = (const char*)Asrc;

    auto load_chunk = [&](int chunk, int st) {
        uint32_t sb = sbase + st * STAGE_BYTES;
        uint32_t ko = (uint32_t)(kbase + chunk) * 128u;   // 64 fp16 = 128B
#pragma unroll
        for (int j = 0; j < 8; j++) cp16(sb + aSw[j], aSrcC + aOff[j] + ko);
#pragma unroll
        for (int h = 0; h < 2; h++) {
            uint32_t sbb = sb + OFF_B + h * 8192;
            uint32_t koh = ko + h * 64;            // half-chunk: +32 fp16 = 64B
#pragma unroll
            for (int j = 0; j < 4; j++) cp16(sbb + bSw[j], bSrc + bOff[j] + koh);
        }
        CP_COMMIT();
    };

    float acc[4][4][4];
#pragma unroll
    for (int i = 0; i < 4; i++)
#pragma unroll
        for (int j = 0; j < 4; j++)
#pragma unroll
            for (int c = 0; c < 4; c++) acc[i][j][c] = 0.f;

    load_chunk(0, 0);
    load_chunk(1, 1);

    // ldmatrix lane addressing
    const int aRow = lid & 15;
    const int aHi16 = ((lid >> 4) & 1) * 16;
    const int bRowSel = ((lid >> 4) & 1) * 8 + (lid & 7);
    const int bHi16 = ((lid >> 3) & 1) * 16;

    for (int k = 0; k < NC; k++) {
        const int st = k % N_STAGES;
        if (k < NC - 1) asm volatile("cp.async.wait_group 1;" ::: "memory");
        else            asm volatile("cp.async.wait_group 0;" ::: "memory");
        __syncthreads();
        if (k + 2 < NC) load_chunk(k + 2, (k + 2) % N_STAGES);

        const uint32_t tA = sbase + st * STAGE_BYTES;

#pragma unroll
        for (int q = 0; q < 4; q++) {              // 4 k16 steps per K64 chunk
            const uint32_t tB = tA + OFF_B + (q >> 1) * 8192;   // B half-chunk
            const int qq = q & 1;
            uint32_t ah[4][4], bh[2][4], bl[2][4];
#pragma unroll
            for (int mi = 0; mi < 4; mi++) {
                uint32_t adr = sw_addr(tA, wm + mi * 16 + aRow, q * 32 + aHi16);
                ldsm4(ah[mi], adr);
            }
#pragma unroll
            for (int nj2 = 0; nj2 < 2; nj2++) {
                uint32_t adr = sw_addr(tB, wn + nj2 * 16 + bRowSel, qq * 32 + bHi16);
                ldsm4(bh[nj2], adr);
            }
#pragma unroll
            for (int nj2 = 0; nj2 < 2; nj2++) {
                uint32_t adr = sw_addr(tB, wn + nj2 * 16 + bRowSel, 64 + qq * 32 + bHi16);
                ldsm4(bl[nj2], adr);
            }
#pragma unroll
            for (int mi = 0; mi < 4; mi++)
#pragma unroll
                for (int nj = 0; nj < 4; nj++) {
                    uint32_t b0 = bh[nj >> 1][(nj & 1) * 2];
                    uint32_t b1 = bh[nj >> 1][(nj & 1) * 2 + 1];
                    uint32_t l0 = bl[nj >> 1][(nj & 1) * 2];
                    uint32_t l1 = bl[nj >> 1][(nj & 1) * 2 + 1];
                    mma16816(acc[mi][nj], ah[mi], b0, b1);
                    mma16816(acc[mi][nj], ah[mi], l0, l1);
                }
        }
    }

    // ---- epilogue ----
    const float* bp = bias + (size_t)e * Ndim + n0;
    const bool addb = IS_FC || (ksplit == 0);
    const int rbase = wm + (lid >> 2);
    const int cquad = (lid & 3) * 2;

#pragma unroll
    for (int mi = 0; mi < 4; mi++) {
#pragma unroll
        for (int half = 0; half < 2; half++) {
            const int row = rbase + mi * 16 + half * 8;
            const int m = m0 + row;
            if (m >= cnt) continue;
            const int slot = off + m;
            int tok = 0; float wgt = 0.f;
            if (!IS_FC) { tok = g_slot_token[slot]; wgt = g_slot_w[slot]; }
#pragma unroll
            for (int nj = 0; nj < 4; nj++) {
                const int col = wn + nj * 8 + cquad;
                float b0 = addb ? bp[col] : 0.f;
                float b1 = addb ? bp[col + 1] : 0.f;
                float v0 = acc[mi][nj][half * 2 + 0] + b0;
                float v1 = acc[mi][nj][half * 2 + 1] + b1;
                if (IS_FC) {
                    float g0 = 0.5f * v0 * (1.f + erff(v0 * 0.70710678118654752f));
                    float g1 = 0.5f * v1 * (1.f + erff(v1 * 0.70710678118654752f));
                    __half h0 = __float2half(g0);
                    __half h1 = __float2half(g1);
                    size_t idx = (size_t)slot * Ndim + n0 + col;
                    *(uint32_t*)(g_h + idx) =
                        (uint32_t)__half_as_ushort(h0) |
                        ((uint32_t)__half_as_ushort(h1) << 16);
                } else {
                    float* op = out + (size_t)tok * D_DIM + n0 + col;
                    atomicAdd(op + 0, v0 * wgt);
                    atomicAdd(op + 1, v1 * wgt);
                }
            }
        }
    }
}

// ------------------------------------------------------------------ launch
extern "C" void kernel_launch(void* const* d_in, const int* in_sizes, int n_in,
                              void* d_out, int out_size)
{
    const float* x      = (const float*)d_in[0];
    const float* rw     = (const float*)d_in[1];
    const float* w_fc   = (const float*)d_in[2];
    const float* b_fc   = (const float*)d_in[3];
    const float* w_proj = (const float*)d_in[4];
    const float* b_proj = (const float*)d_in[5];
    float* out = (float*)d_out;

    cudaFuncSetAttribute(k_mma_gemm<true>,  cudaFuncAttributeMaxDynamicSharedMemorySize, GEMM_SMEM);
    cudaFuncSetAttribute(k_mma_gemm<false>, cudaFuncAttributeMaxDynamicSharedMemorySize, GEMM_SMEM);

    cudaMemsetAsync(out, 0, (size_t)out_size * sizeof(float));
    void* pfill = nullptr;
    cudaGetSymbolAddress(&pfill, g_fill);
    cudaMemsetAsync(pfill, 0, E_EXP * sizeof(int));

    dim3 bw(32, 8);
    k_convw<<<dim3(F_DIM / 32, D_DIM / 32, E_EXP), bw>>>(w_fc,   D_DIM, F_DIM, 0);  // #1
    k_convw<<<dim3(D_DIM / 32, F_DIM / 32, E_EXP), bw>>>(w_proj, F_DIM, D_DIM, 1);  // #2

    k_router<<<T_TOKENS / 8, 256>>>(x, rw);                                          // #3

    // gemm1: CTA tile 128x64                                               #4 (profiled)
    k_mma_gemm<true ><<<dim3(EXP_CAP / 128, F_DIM / 64, E_EXP), 128, GEMM_SMEM>>>(b_fc, nullptr);
    // gemm2: split-K x2 -> grid.z = 2*experts                              #5
    k_mma_gemm<false><<<dim3(EXP_CAP / 128, D_DIM / 64, E_EXP * 2), 128, GEMM_SMEM>>>(b_proj, out);
}

// round 9
// speedup vs baseline: 2.3936x; 1.7660x over previous
#include <cuda_runtime.h>
#include <cuda_fp16.h>
#include <math.h>
#include <stdint.h>

#define T_TOKENS 4096
#define D_DIM    768
#define F_DIM    3072
#define E_EXP    8
#define EXP_CAP  4096
#define NSLOTS   (E_EXP * EXP_CAP)

// ------------------------------------------------------------------ scratch
__device__ int   g_fill[E_EXP];          // zeroed by memset each call
__device__ int   g_slot_token[NSLOTS];
__device__ float g_slot_w[NSLOTS];

__device__ __half g_a[(size_t)NSLOTS * D_DIM];   // x gathered, fp16
__device__ __half g_h[(size_t)NSLOTS * F_DIM];   // gelu(fc), fp16
// transposed K-major fp16 weights: wfcT [E][F][D], wpjT [E][D][F]
__device__ __half g_wfc[(size_t)E_EXP * F_DIM * D_DIM];
__device__ __half g_wpj[(size_t)E_EXP * D_DIM * F_DIM];

// ------------------------------------------------------------------ helpers
__device__ __forceinline__ uint32_t smem_u32(const void* p) {
    uint32_t a;
    asm("{ .reg .u64 t; cvta.to.shared.u64 t, %1; cvt.u32.u64 %0, t; }" : "=r"(a) : "l"(p));
    return a;
}
__device__ __forceinline__ void cp16(uint32_t s, const void* g) {
    asm volatile("cp.async.cg.shared.global [%0], [%1], 16;" :: "r"(s), "l"(g));
}
#define CP_COMMIT() asm volatile("cp.async.commit_group;" ::: "memory")

__device__ __forceinline__ void ldsm4(uint32_t r[4], uint32_t addr) {
    asm volatile("ldmatrix.sync.aligned.m8n8.x4.shared.b16 {%0,%1,%2,%3}, [%4];"
                 : "=r"(r[0]), "=r"(r[1]), "=r"(r[2]), "=r"(r[3]) : "r"(addr));
}
__device__ __forceinline__ void mma16816(float c[4], const uint32_t a[4],
                                         uint32_t b0, uint32_t b1) {
    asm volatile("mma.sync.aligned.m16n8k16.row.col.f32.f16.f16.f32 "
                 "{%0,%1,%2,%3}, {%4,%5,%6,%7}, {%8,%9}, {%0,%1,%2,%3};"
                 : "+f"(c[0]), "+f"(c[1]), "+f"(c[2]), "+f"(c[3])
                 : "r"(a[0]), "r"(a[1]), "r"(a[2]), "r"(a[3]), "r"(b0), "r"(b1));
}

// ------------------------------------------------------------------ weight convert
// transpose: src [E][K][N] fp32 -> dst [E][N][K] fp16
__global__ void k_convw(const float* __restrict__ src, int K, int N, int which) {
    __shared__ float tile[32][33];
    __half* dst = which ? g_wpj : g_wfc;
    int e = blockIdx.z;
    int n0 = blockIdx.x * 32, k0 = blockIdx.y * 32;
    const float* s = src + (size_t)e * K * N;
#pragma unroll
    for (int dy = 0; dy < 32; dy += 8)
        tile[threadIdx.y + dy][threadIdx.x] =
            s[(size_t)(k0 + threadIdx.y + dy) * N + n0 + threadIdx.x];
    __syncthreads();
    size_t db = (size_t)e * N * K;
#pragma unroll
    for (int dy = 0; dy < 32; dy += 8) {
        int n = n0 + threadIdx.y + dy, k = k0 + threadIdx.x;
        dst[db + (size_t)n * K + k] = __float2half(tile[threadIdx.x][threadIdx.y + dy]);
    }
}

// ------------------------------------------------------------------ fused router + slot fill + x->fp16
__global__ void k_router(const float* __restrict__ x, const float* __restrict__ rw) {
    __shared__ float s_rw[E_EXP * D_DIM];
    for (int i = threadIdx.x; i < E_EXP * D_DIM; i += blockDim.x) s_rw[i] = rw[i];
    __syncthreads();
    int warp = threadIdx.x >> 5, lane = threadIdx.x & 31;
    int t = blockIdx.x * 8 + warp;
    if (t >= T_TOKENS) return;

    const float* xrow = x + (size_t)t * D_DIM;
    float xr[24];
#pragma unroll
    for (int i = 0; i < 24; i++) xr[i] = xrow[lane + 32 * i];

    float logit[E_EXP];
#pragma unroll
    for (int e = 0; e < E_EXP; e++) {
        float p = 0.f;
#pragma unroll
        for (int i = 0; i < 24; i++) p = fmaf(xr[i], s_rw[e * D_DIM + lane + 32 * i], p);
#pragma unroll
        for (int o = 16; o; o >>= 1) p += __shfl_xor_sync(0xffffffffu, p, o);
        logit[e] = p;
    }
    int slot0 = 0, slot1 = 0;
    if (lane == 0) {
        int e0 = 0; float v0 = logit[0];
#pragma unroll
        for (int e = 1; e < E_EXP; e++) if (logit[e] > v0) { v0 = logit[e]; e0 = e; }
        int e1 = 0; float v1 = -3.0e38f;
#pragma unroll
        for (int e = 0; e < E_EXP; e++) {
            if (e == e0) continue;
            if (logit[e] > v1) { v1 = logit[e]; e1 = e; }
        }
        float ex = expf(v1 - v0);
        float inv = 1.f / (1.f + ex);
        slot0 = e0 * EXP_CAP + atomicAdd(&g_fill[e0], 1);
        slot1 = e1 * EXP_CAP + atomicAdd(&g_fill[e1], 1);
        g_slot_token[slot0] = t;  g_slot_w[slot0] = inv;
        g_slot_token[slot1] = t;  g_slot_w[slot1] = ex * inv;
    }
    slot0 = __shfl_sync(0xffffffffu, slot0, 0);
    slot1 = __shfl_sync(0xffffffffu, slot1, 0);

#pragma unroll
    for (int i = 0; i < 24; i++) {
        __half h = __float2half(xr[i]);
        int c = lane + 32 * i;
        g_a[(size_t)slot0 * D_DIM + c] = h;
        g_a[(size_t)slot1 * D_DIM + c] = h;
    }
}

// ------------------------------------------------------------------ mma.sync grouped GEMM
// CTA 128x64, 4 warps (warp tile 64x32), single-pass fp16 A*B.
// Chunk = K64. Stage 24KB: A 128x128B + B 64x128B, both SW128 K-major.
// 3 stages (72KB) -> 3 CTAs/SM. gemm2 uses split-K x2 (atomicAdd combine).
#define OFF_B 16384
#define STAGE_BYTES 24576
#define N_STAGES 3
#define GEMM_SMEM (N_STAGES * STAGE_BYTES + 1024)

__device__ __forceinline__ uint32_t sw_addr(uint32_t tbase, int row, int byte) {
    uint32_t b = (uint32_t)(row * 128 + byte);
    return tbase + (b ^ ((b >> 3) & 0x70));
}

template <bool IS_FC>
__global__ __launch_bounds__(128, 3)
void k_mma_gemm(const float* __restrict__ bias, float* __restrict__ out)
{
    constexpr int Kdim = IS_FC ? D_DIM : F_DIM;
    constexpr int Ndim = IS_FC ? F_DIM : D_DIM;
    constexpr int NC   = IS_FC ? (Kdim / 64) : (Kdim / 64 / 2);   // K64 chunks this CTA

    const int zz     = blockIdx.z;
    const int e      = IS_FC ? zz : (zz >> 1);
    const int ksplit = IS_FC ? 0 : (zz & 1);
    const int kbase  = ksplit * NC;

    const int cnt = g_fill[e];
    const int off = e * EXP_CAP;
    const int m0  = blockIdx.x * 128;
    if (m0 >= cnt) return;
    const int n0 = blockIdx.y * 64;

    const __half* Asrc = IS_FC ? g_a : g_h;
    const __half* Bsrc = (IS_FC ? g_wfc : g_wpj) + (size_t)e * Ndim * Kdim;

    extern __shared__ char smem_raw[];
    const uint32_t sbase = (smem_u32(smem_raw) + 1023) & ~1023u;

    const int tid = threadIdx.x;
    const int wid = tid >> 5, lid = tid & 31;
    const int wm = (wid >> 1) * 64;     // 2x2 warp grid over 128x64
    const int wn = (wid & 1) * 32;

    // ---- load mappings: K-major rows of 128B (64 fp16); c16 = tid&7 ----
    const int c16 = tid & 7;
    uint32_t aOff[8], aSw[8], bOff[4], bSw[4];
#pragma unroll
    for (int j = 0; j < 8; j++) {
        int row = (tid >> 3) + j * 16;             // 0..127
        int gr  = off + min(m0 + row, cnt - 1);
        aOff[j] = (uint32_t)gr * (uint32_t)(Kdim * 2) + (uint32_t)(c16 * 16);
        uint32_t b = (uint32_t)(row * 128 + c16 * 16);
        aSw[j] = b ^ ((b >> 3) & 0x70);
    }
#pragma unroll
    for (int j = 0; j < 4; j++) {
        int row = (tid >> 3) + j * 16;             // 0..63
        bOff[j] = (uint32_t)(n0 + row) * (uint32_t)(Kdim * 2) + (uint32_t)(c16 * 16);
        uint32_t b = (uint32_t)(row * 128 + c16 * 16);
        bSw[j] = b ^ ((b >> 3) & 0x70);
    }
    const char* aSrcC = (const char*)Asrc;
    const char* bSrcC = (const char*)Bsrc;

    auto load_chunk = [&](int chunk, int st) {
        uint32_t sb = sbase + st * STAGE_BYTES;
        uint32_t ko = (uint32_t)(kbase + chunk) * 128u;   // 64 fp16 = 128B
#pragma unroll
        for (int j = 0; j < 8; j++) cp16(sb + aSw[j], aSrcC + aOff[j] + ko);
#pragma unroll
        for (int j = 0; j < 4; j++) cp16(sb + OFF_B + bSw[j], bSrcC + bOff[j] + ko);
        CP_COMMIT();
    };

    float acc[4][4][4];
#pragma unroll
    for (int i = 0; i < 4; i++)
#pragma unroll
        for (int j = 0; j < 4; j++)
#pragma unroll
            for (int c = 0; c < 4; c++) acc[i][j][c] = 0.f;

    load_chunk(0, 0);
    load_chunk(1, 1);

    // ldmatrix lane addressing
    const int aRow = lid & 15;
    const int aHi16 = ((lid >> 4) & 1) * 16;
    const int bRowSel = ((lid >> 4) & 1) * 8 + (lid & 7);
    const int bHi16 = ((lid >> 3) & 1) * 16;

    for (int k = 0; k < NC; k++) {
        const int st = k % N_STAGES;
        if (k < NC - 1) asm volatile("cp.async.wait_group 1;" ::: "memory");
        else            asm volatile("cp.async.wait_group 0;" ::: "memory");
        __syncthreads();
        if (k + 2 < NC) load_chunk(k + 2, (k + 2) % N_STAGES);

        const uint32_t tA = sbase + st * STAGE_BYTES;
        const uint32_t tB = tA + OFF_B;

#pragma unroll
        for (int q = 0; q < 4; q++) {              // 4 k16 steps per K64 chunk
            uint32_t ah[4][4], bh[2][4];
#pragma unroll
            for (int mi = 0; mi < 4; mi++) {
                uint32_t adr = sw_addr(tA, wm + mi * 16 + aRow, q * 32 + aHi16);
                ldsm4(ah[mi], adr);
            }
#pragma unroll
            for (int nj2 = 0; nj2 < 2; nj2++) {
                uint32_t adr = sw_addr(tB, wn + nj2 * 16 + bRowSel, q * 32 + bHi16);
                ldsm4(bh[nj2], adr);
            }
#pragma unroll
            for (int mi = 0; mi < 4; mi++)
#pragma unroll
                for (int nj = 0; nj < 4; nj++) {
                    uint32_t b0 = bh[nj >> 1][(nj & 1) * 2];
                    uint32_t b1 = bh[nj >> 1][(nj & 1) * 2 + 1];
                    mma16816(acc[mi][nj], ah[mi], b0, b1);
                }
        }
    }

    // ---- epilogue ----
    const float* bp = bias + (size_t)e * Ndim + n0;
    const bool addb = IS_FC || (ksplit == 0);
    const int rbase = wm + (lid >> 2);
    const int cquad = (lid & 3) * 2;

#pragma unroll
    for (int mi = 0; mi < 4; mi++) {
#pragma unroll
        for (int half = 0; half < 2; half++) {
            const int row = rbase + mi * 16 + half * 8;
            const int m = m0 + row;
            if (m >= cnt) continue;
            const int slot = off + m;
            int tok = 0; float wgt = 0.f;
            if (!IS_FC) { tok = g_slot_token[slot]; wgt = g_slot_w[slot]; }
#pragma unroll
            for (int nj = 0; nj < 4; nj++) {
                const int col = wn + nj * 8 + cquad;
                float b0 = addb ? bp[col] : 0.f;
                float b1 = addb ? bp[col + 1] : 0.f;
                float v0 = acc[mi][nj][half * 2 + 0] + b0;
                float v1 = acc[mi][nj][half * 2 + 1] + b1;
                if (IS_FC) {
                    float g0 = 0.5f * v0 * (1.f + erff(v0 * 0.70710678118654752f));
                    float g1 = 0.5f * v1 * (1.f + erff(v1 * 0.70710678118654752f));
                    __half h0 = __float2half(g0);
                    __half h1 = __float2half(g1);
                    size_t idx = (size_t)slot * Ndim + n0 + col;
                    *(uint32_t*)(g_h + idx) =
                        (uint32_t)__half_as_ushort(h0) |
                        ((uint32_t)__half_as_ushort(h1) << 16);
                } else {
                    float* op = out + (size_t)tok * D_DIM + n0 + col;
                    atomicAdd(op + 0, v0 * wgt);
                    atomicAdd(op + 1, v1 * wgt);
                }
            }
        }
    }
}

// ------------------------------------------------------------------ launch
extern "C" void kernel_launch(void* const* d_in, const int* in_sizes, int n_in,
                              void* d_out, int out_size)
{
    const float* x      = (const float*)d_in[0];
    const float* rw     = (const float*)d_in[1];
    const float* w_fc   = (const float*)d_in[2];
    const float* b_fc   = (const float*)d_in[3];
    const float* w_proj = (const float*)d_in[4];
    const float* b_proj = (const float*)d_in[5];
    float* out = (float*)d_out;

    cudaFuncSetAttribute(k_mma_gemm<true>,  cudaFuncAttributeMaxDynamicSharedMemorySize, GEMM_SMEM);
    cudaFuncSetAttribute(k_mma_gemm<false>, cudaFuncAttributeMaxDynamicSharedMemorySize, GEMM_SMEM);

    cudaMemsetAsync(out, 0, (size_t)out_size * sizeof(float));
    void* pfill = nullptr;
    cudaGetSymbolAddress(&pfill, g_fill);
    cudaMemsetAsync(pfill, 0, E_EXP * sizeof(int));

    dim3 bw(32, 8);
    k_convw<<<dim3(F_DIM / 32, D_DIM / 32, E_EXP), bw>>>(w_fc,   D_DIM, F_DIM, 0);  // #1
    k_convw<<<dim3(D_DIM / 32, F_DIM / 32, E_EXP), bw>>>(w_proj, F_DIM, D_DIM, 1);  // #2

    k_router<<<T_TOKENS / 8, 256>>>(x, rw);                                          // #3

    // gemm1: CTA tile 128x64                                               #4 (profiled)
    k_mma_gemm<true ><<<dim3(EXP_CAP / 128, F_DIM / 64, E_EXP), 128, GEMM_SMEM>>>(b_fc, nullptr);
    // gemm2: split-K x2 -> grid.z = 2*experts                              #5
    k_mma_gemm<false><<<dim3(EXP_CAP / 128, D_DIM / 64, E_EXP * 2), 128, GEMM_SMEM>>>(b_proj, out);
}